// round 16
// baseline (speedup 1.0000x reference)
#include <cuda_runtime.h>
#include <cstdint>

#define N_TOK 2304
#define DIMX 384
#define NHEADS 8
#define KD 32
#define DV 128
#define DH 1024
#define RES 48
#define SCALE_F 0.17677669529663687f

// Scratch (allocation-free rule: __device__ globals)
// g_Q/g_K/g_V/g_O/g_Wp hold tf32-rounded bit patterns.
__device__ float g_Q[NHEADS * N_TOK * KD];
__device__ float g_K[NHEADS * N_TOK * KD];
__device__ float g_V[NHEADS * N_TOK * DV];
__device__ float g_O[N_TOK * DH];              // tf32 bits (attn output)
__device__ float g_Wp[DIMX * DH];              // tf32 bits (proj_w converted)

// ---------------------------------------------------------------------------
// helpers
// ---------------------------------------------------------------------------
__device__ __forceinline__ uint32_t f2tf(float f) {
    uint32_t u;
    asm("cvt.rna.tf32.f32 %0, %1;" : "=r"(u) : "f"(f));
    return u;
}

__device__ __forceinline__ void mma8(float* d,
                                     uint32_t a0, uint32_t a1, uint32_t a2, uint32_t a3,
                                     uint32_t b0, uint32_t b1)
{
    asm volatile(
        "mma.sync.aligned.m16n8k8.row.col.f32.tf32.tf32.f32 "
        "{%0,%1,%2,%3}, {%4,%5,%6,%7}, {%8,%9}, {%0,%1,%2,%3};\n"
        : "+f"(d[0]), "+f"(d[1]), "+f"(d[2]), "+f"(d[3])
        : "r"(a0), "r"(a1), "r"(a2), "r"(a3), "r"(b0), "r"(b1));
}

__device__ __forceinline__ void cp16(uint32_t* smem_dst, const void* gsrc) {
    uint32_t sa = (uint32_t)__cvta_generic_to_shared(smem_dst);
    asm volatile("cp.async.cg.shared.global [%0], [%1], 16;\n" :: "r"(sa), "l"(gsrc));
}
__device__ __forceinline__ void cp_commit() {
    asm volatile("cp.async.commit_group;\n");
}
template <int N>
__device__ __forceinline__ void cp_wait() {
    asm volatile("cp.async.wait_group %0;\n" :: "n"(N));
}

// ---------------------------------------------------------------------------
// Kernel 0: convert proj_w to tf32 bits (one shot, ~2 us).
// ---------------------------------------------------------------------------
__global__ __launch_bounds__(256) void conv_w(const float* __restrict__ Wp)
{
    int i = blockIdx.x * 256 + threadIdx.x;      // 98304 float4s
    float4 w = ((const float4*)Wp)[i];
    uint4 u = {f2tf(w.x), f2tf(w.y), f2tf(w.z), f2tf(w.w)};
    ((uint4*)g_Wp)[i] = u;
}

// ---------------------------------------------------------------------------
// Kernel 1: fused QKV projection — exact R10 form (proven).
// ---------------------------------------------------------------------------
__global__ __launch_bounds__(256) void qkv_mma(
    const float* __restrict__ x,
    const float* __restrict__ q_w, const float* __restrict__ q_b,
    const float* __restrict__ k_w, const float* __restrict__ k_b,
    const float* __restrict__ v_w, const float* __restrict__ v_b)
{
    __shared__ __align__(16) uint32_t sA[128 * 36];
    __shared__ __align__(16) uint32_t sB[64 * 36];

    const int tid  = threadIdx.x;
    const int warp = tid >> 5, lane = tid & 31;
    const int g = lane >> 2, t = lane & 3;
    const int warpM = warp & 3;
    const int warpN = warp >> 2;
    const int rowBase = blockIdx.x * 128;
    const int colBase = blockIdx.y * 64;

    const float* W; const float* bias; int sel, wBase;
    if (colBase < 256)      { W = q_w; bias = q_b; sel = 0; wBase = colBase;       }
    else if (colBase < 512) { W = k_w; bias = k_b; sel = 1; wBase = colBase - 256; }
    else                    { W = v_w; bias = v_b; sel = 2; wBase = colBase - 512; }

    float acc[2][4][4];
    #pragma unroll
    for (int mt = 0; mt < 2; mt++)
        #pragma unroll
        for (int nt = 0; nt < 4; nt++)
            #pragma unroll
            for (int j = 0; j < 4; j++) acc[mt][nt][j] = 0.f;

    for (int k0 = 0; k0 < DIMX; k0 += 32) {
        #pragma unroll
        for (int it = 0; it < 4; it++) {
            int i = tid + it * 256;
            int r = i >> 3, c = (i & 7) << 2;
            float4 a = *(const float4*)(x + (rowBase + r) * DIMX + k0 + c);
            uint4 u = {f2tf(a.x), f2tf(a.y), f2tf(a.z), f2tf(a.w)};
            *(uint4*)&sA[r * 36 + c] = u;
        }
        #pragma unroll
        for (int it = 0; it < 2; it++) {
            int i = tid + it * 256;
            int r = i >> 3, c = (i & 7) << 2;
            float4 b = *(const float4*)(W + (wBase + r) * DIMX + k0 + c);
            uint4 u = {f2tf(b.x), f2tf(b.y), f2tf(b.z), f2tf(b.w)};
            *(uint4*)&sB[r * 36 + c] = u;
        }
        __syncthreads();

        #pragma unroll
        for (int kk = 0; kk < 4; kk++) {
            uint32_t af[2][4], bf[4][2];
            #pragma unroll
            for (int mt = 0; mt < 2; mt++) {
                int row = warpM * 32 + mt * 16;
                af[mt][0] = sA[(row + g) * 36 + kk * 8 + t];
                af[mt][1] = sA[(row + 8 + g) * 36 + kk * 8 + t];
                af[mt][2] = sA[(row + g) * 36 + kk * 8 + t + 4];
                af[mt][3] = sA[(row + 8 + g) * 36 + kk * 8 + t + 4];
            }
            #pragma unroll
            for (int nt = 0; nt < 4; nt++) {
                int col = warpN * 32 + nt * 8;
                bf[nt][0] = sB[(col + g) * 36 + kk * 8 + t];
                bf[nt][1] = sB[(col + g) * 36 + kk * 8 + t + 4];
            }
            #pragma unroll
            for (int mt = 0; mt < 2; mt++)
                #pragma unroll
                for (int nt = 0; nt < 4; nt++)
                    mma8(acc[mt][nt], af[mt][0], af[mt][1], af[mt][2], af[mt][3],
                         bf[nt][0], bf[nt][1]);
        }
        __syncthreads();
    }

    #pragma unroll
    for (int nt = 0; nt < 4; nt++) {
        int jl = wBase + warpN * 32 + nt * 8 + 2 * t;
        float b0v = bias[jl], b1v = bias[jl + 1];
        #pragma unroll
        for (int mt = 0; mt < 2; mt++) {
            int row0 = rowBase + warpM * 32 + mt * 16 + g;
            int row1 = row0 + 8;
            float2 lo = {__uint_as_float(f2tf(acc[mt][nt][0] + b0v)),
                         __uint_as_float(f2tf(acc[mt][nt][1] + b1v))};
            float2 hi = {__uint_as_float(f2tf(acc[mt][nt][2] + b0v)),
                         __uint_as_float(f2tf(acc[mt][nt][3] + b1v))};
            if (sel == 0) {
                int h = jl >> 5, kd = jl & 31;
                *(float2*)&g_Q[(h * N_TOK + row0) * KD + kd] = lo;
                *(float2*)&g_Q[(h * N_TOK + row1) * KD + kd] = hi;
            } else if (sel == 1) {
                int h = jl >> 5, kd = jl & 31;
                *(float2*)&g_K[(h * N_TOK + row0) * KD + kd] = lo;
                *(float2*)&g_K[(h * N_TOK + row1) * KD + kd] = hi;
            } else {
                int h = jl >> 7, dv = jl & 127;
                *(float2*)&g_V[(h * N_TOK + row0) * DV + dv] = lo;
                *(float2*)&g_V[(h * N_TOK + row1) * DV + dv] = hi;
            }
        }
    }
}

// ---------------------------------------------------------------------------
// Kernel 2: flash attention. BQ=64, 256 threads (8 warps), 89.6 KB smem ->
// TRUE 2 CTAs/SM = 16 warps/SM. Warp: rg=warp>>1 owns 16 rows (softmax math
// identical to R6), cg=warp&1 owns 64 V-cols. S duplicated across cg twins;
// sS written disjointly (cg0: cols 0..31, cg1: 32..63). alpha/l stay in regs
// (PV rows == softmax rows). K double-buffered, V single + deferred wait.
// ---------------------------------------------------------------------------
#define KBUF (64 * 36)
#define AT_SQ     0                        // 64*36 = 2304
#define AT_SK     (AT_SQ + 64 * 36)        // 2 x 2304
#define AT_SV     (AT_SK + 2 * KBUF)       // 64*136 = 8704
#define AT_SS     (AT_SV + 64 * 136)       // 64*68 = 4352
#define AT_SBIAS  (AT_SS + 64 * 68)        // 2304
#define AT_TOTAL  (AT_SBIAS + N_TOK)       // 22272 u32 = 89088 bytes

__global__ __launch_bounds__(256, 2) void attn_mma(
    const float* __restrict__ biases)
{
    extern __shared__ __align__(16) uint32_t smu[];
    uint32_t* sQ  = smu + AT_SQ;
    uint32_t* sKb = smu + AT_SK;
    uint32_t* sV  = smu + AT_SV;
    uint32_t* sS  = smu + AT_SS;
    float*    sBias = (float*)(smu + AT_SBIAS);

    const int tid  = threadIdx.x;
    const int warp = tid >> 5, lane = tid & 31;
    const int g = lane >> 2, t = lane & 3;
    const int rg = warp >> 1;            // row group 0..3 (16 rows each)
    const int cg = warp & 1;             // col group 0..1 (64 V cols each)
    const int h  = blockIdx.y;
    const int q0 = blockIdx.x * 64;

    const uint32_t* gK = (const uint32_t*)(g_K + h * N_TOK * KD);
    const uint32_t* gV = (const uint32_t*)(g_V + h * N_TOK * DV);

    // --- prologue: Q tile + bias -> smem, prefetch K(0) ---
    {
        const uint4* src = (const uint4*)(g_Q + (h * N_TOK + q0) * KD);
        #pragma unroll
        for (int it = 0; it < 2; it++) {
            int i = tid + it * 256;          // 512 uint4s
            int r = i >> 3, c = (i & 7) << 2;
            *(uint4*)&sQ[r * 36 + c] = src[i];
        }
        #pragma unroll
        for (int it = 0; it < 9; it++)
            sBias[tid + it * 256] = biases[h * N_TOK + tid + it * 256];
        #pragma unroll
        for (int it = 0; it < 2; it++) {
            int i = tid + it * 256;          // 512 cp16s
            int r = i >> 3, c = (i & 7) << 2;
            cp16(&sKb[r * 36 + c], gK + i * 4);
        }
        cp_commit();
    }
    __syncthreads();   // sQ visible

    // --- Q fragments, register resident (rg rows) ---
    uint32_t qf[4][4];
    {
        int row = 16 * rg + g;
        #pragma unroll
        for (int kk = 0; kk < 4; kk++) {
            qf[kk][0] = sQ[row * 36 + kk * 8 + t];
            qf[kk][1] = sQ[(row + 8) * 36 + kk * 8 + t];
            qf[kk][2] = sQ[row * 36 + kk * 8 + t + 4];
            qf[kk][3] = sQ[(row + 8) * 36 + kk * 8 + t + 4];
        }
    }

    float m0 = -1e30f, m1 = -1e30f, l0 = 0.f, l1 = 0.f;

    const int rowW = 16 * rg + g;
    const int gRow0 = q0 + rowW;
    const int gRow1 = gRow0 + 8;
    const int qy0 = gRow0 / RES, qx0 = gRow0 - qy0 * RES;
    const int qy1 = gRow1 / RES, qx1 = gRow1 - qy1 * RES;
    const int pcol = cg * 64;            // this warp's V column base

    float o[8][4];
    #pragma unroll
    for (int vt = 0; vt < 8; vt++)
        #pragma unroll
        for (int j = 0; j < 4; j++) o[vt][j] = 0.f;

    const int NITER = N_TOK / 64;   // 36

    for (int ki = 0; ki < NITER; ki++) {
        const int cur = ki & 1, nxt = cur ^ 1;
        const bool hasNext = (ki + 1 < NITER);

        // issue V(ki) into single V buffer (trailing barrier guards reuse)
        {
            const uint32_t* gVn = gV + ki * 64 * DV;
            #pragma unroll
            for (int it = 0; it < 8; it++) {
                int i = tid + it * 256;      // 2048 cp16s
                int r = i >> 5, c = (i & 31) << 2;
                cp16(&sV[r * 136 + c], gVn + i * 4);
            }
            cp_commit();
        }
        // issue K(ki+1)
        if (hasNext) {
            const uint32_t* gKn = gK + (ki + 1) * 64 * KD;
            #pragma unroll
            for (int it = 0; it < 2; it++) {
                int i = tid + it * 256;
                int r = i >> 3, c = (i & 7) << 2;
                cp16(&sKb[nxt * KBUF + r * 36 + c], gKn + i * 4);
            }
            cp_commit();
        }
        // wait for K(ki); leave V(ki) [+ K(ki+1)] in flight
        if (hasNext) cp_wait<2>(); else cp_wait<1>();
        __syncthreads();

        const uint32_t* sK = sKb + cur * KBUF;
        const int k0 = ki * 64;

        // --- S = Q @ K^T (16 rows x 64 cols; duplicated across cg twins) ---
        float sreg[8][4];
        #pragma unroll
        for (int nt = 0; nt < 8; nt++) {
            float s4[4] = {0.f, 0.f, 0.f, 0.f};
            #pragma unroll
            for (int kk = 0; kk < 4; kk++) {
                uint32_t b0 = sK[(nt * 8 + g) * 36 + kk * 8 + t];
                uint32_t b1 = sK[(nt * 8 + g) * 36 + kk * 8 + t + 4];
                mma8(s4, qf[kk][0], qf[kk][1], qf[kk][2], qf[kk][3], b0, b1);
            }
            int c0 = k0 + nt * 8 + 2 * t;
            int c1 = c0 + 1;
            int ky0 = c0 / RES, kx0 = c0 - ky0 * RES;
            int ky1 = c1 / RES, kx1 = c1 - ky1 * RES;
            sreg[nt][0] = s4[0] * SCALE_F + sBias[abs(qy0 - ky0) * RES + abs(qx0 - kx0)];
            sreg[nt][1] = s4[1] * SCALE_F + sBias[abs(qy0 - ky1) * RES + abs(qx0 - kx1)];
            sreg[nt][2] = s4[2] * SCALE_F + sBias[abs(qy1 - ky0) * RES + abs(qx1 - kx0)];
            sreg[nt][3] = s4[3] * SCALE_F + sBias[abs(qy1 - ky1) * RES + abs(qx1 - kx1)];
        }

        // --- online softmax, warp-local (duplicated across cg twins) ---
        float mx0 = m0, mx1 = m1;
        #pragma unroll
        for (int nt = 0; nt < 8; nt++) {
            mx0 = fmaxf(mx0, fmaxf(sreg[nt][0], sreg[nt][1]));
            mx1 = fmaxf(mx1, fmaxf(sreg[nt][2], sreg[nt][3]));
        }
        mx0 = fmaxf(mx0, __shfl_xor_sync(0xffffffffu, mx0, 1));
        mx0 = fmaxf(mx0, __shfl_xor_sync(0xffffffffu, mx0, 2));
        mx1 = fmaxf(mx1, __shfl_xor_sync(0xffffffffu, mx1, 1));
        mx1 = fmaxf(mx1, __shfl_xor_sync(0xffffffffu, mx1, 2));
        float a0 = __expf(m0 - mx0), a1 = __expf(m1 - mx1);
        float sum0 = 0.f, sum1 = 0.f;
        #pragma unroll
        for (int nt = 0; nt < 8; nt++) {
            float p0 = __expf(sreg[nt][0] - mx0);
            float p1 = __expf(sreg[nt][1] - mx0);
            float p2 = __expf(sreg[nt][2] - mx1);
            float p3 = __expf(sreg[nt][3] - mx1);
            sum0 += p0 + p1; sum1 += p2 + p3;
            // disjoint sS write: cg0 -> nt 0..3 (cols 0..31), cg1 -> nt 4..7
            if ((nt >> 2) == cg) {
                uint2 u0 = {f2tf(p0), f2tf(p1)};
                uint2 u1 = {f2tf(p2), f2tf(p3)};
                *(uint2*)&sS[rowW * 68 + nt * 8 + 2 * t] = u0;
                *(uint2*)&sS[(rowW + 8) * 68 + nt * 8 + 2 * t] = u1;
            }
        }
        sum0 += __shfl_xor_sync(0xffffffffu, sum0, 1);
        sum0 += __shfl_xor_sync(0xffffffffu, sum0, 2);
        sum1 += __shfl_xor_sync(0xffffffffu, sum1, 1);
        sum1 += __shfl_xor_sync(0xffffffffu, sum1, 2);
        l0 = l0 * a0 + sum0; m0 = mx0;
        l1 = l1 * a1 + sum1; m1 = mx1;

        // wait for V(ki) — latency covered by S + softmax
        if (hasNext) cp_wait<1>(); else cp_wait<0>();
        __syncthreads();   // sS + sV visible

        // --- rescale O with register-resident alphas ---
        #pragma unroll
        for (int vt = 0; vt < 8; vt++) {
            o[vt][0] *= a0; o[vt][1] *= a0;
            o[vt][2] *= a1; o[vt][3] *= a1;
        }

        // --- O += P @ V (warp: 16 rows x 64 cols) ---
        #pragma unroll
        for (int kk = 0; kk < 8; kk++) {
            uint32_t p0 = sS[rowW * 68 + kk * 8 + t];
            uint32_t p1 = sS[(rowW + 8) * 68 + kk * 8 + t];
            uint32_t p2 = sS[rowW * 68 + kk * 8 + t + 4];
            uint32_t p3 = sS[(rowW + 8) * 68 + kk * 8 + t + 4];
            #pragma unroll
            for (int vt = 0; vt < 8; vt++) {
                uint32_t b0 = sV[(kk * 8 + t) * 136 + pcol + vt * 8 + g];
                uint32_t b1 = sV[(kk * 8 + t + 4) * 136 + pcol + vt * 8 + g];
                mma8(o[vt], p0, p1, p2, p3, b0, b1);
            }
        }
        __syncthreads();   // sV + sS reads done before next-iter refill
    }

    // --- finalize with register-resident l ---
    float inv0 = 1.f / l0, inv1 = 1.f / l1;
    #pragma unroll
    for (int vt = 0; vt < 8; vt++) {
        int col = pcol + vt * 8 + 2 * t;
        float2 lo = {__uint_as_float(f2tf(o[vt][0] * inv0)),
                     __uint_as_float(f2tf(o[vt][1] * inv0))};
        float2 hi = {__uint_as_float(f2tf(o[vt][2] * inv1)),
                     __uint_as_float(f2tf(o[vt][3] * inv1))};
        *(float2*)&g_O[(long)gRow0 * DH + h * DV + col] = lo;
        *(float2*)&g_O[(long)gRow1 * DH + h * DV + col] = hi;
    }
}

// ---------------------------------------------------------------------------
// Kernel 3: output projection — unchanged from R10 (30.3 us).
// ---------------------------------------------------------------------------
#define PJBUF (64 * 36)

__global__ __launch_bounds__(256, 2) void proj_mma(
    const float* __restrict__ pb, float* __restrict__ out)
{
    __shared__ __align__(16) uint32_t sAb[2][PJBUF];
    __shared__ __align__(16) uint32_t sBb[2][PJBUF];

    const int tid  = threadIdx.x;
    const int warp = tid >> 5, lane = tid & 31;
    const int g = lane >> 2, t = lane & 3;
    const int warpM = warp & 3;
    const int warpN = warp >> 2;
    const int rowBase = blockIdx.x * 64;
    const int colBase = blockIdx.y * 64;

    const uint32_t* gA = (const uint32_t*)g_O;
    const uint32_t* gB = (const uint32_t*)g_Wp;

    float acc[4][4];
    #pragma unroll
    for (int nt = 0; nt < 4; nt++)
        #pragma unroll
        for (int j = 0; j < 4; j++) acc[nt][j] = 0.f;

    {
        #pragma unroll
        for (int it = 0; it < 2; it++) {
            int i = tid + it * 256;
            int r = i >> 3, c = (i & 7) << 2;
            cp16(&sAb[0][r * 36 + c], gA + (long)(rowBase + r) * DH + c);
            cp16(&sBb[0][r * 36 + c], gB + (long)(colBase + r) * DH + c);
        }
        cp_commit();
    }

    const int NIT = DH / 32;   // 32
    for (int ki = 0; ki < NIT; ki++) {
        const int cur = ki & 1, nxt = cur ^ 1;
        if (ki + 1 < NIT) {
            int k0 = (ki + 1) * 32;
            #pragma unroll
            for (int it = 0; it < 2; it++) {
                int i = tid + it * 256;
                int r = i >> 3, c = (i & 7) << 2;
                cp16(&sAb[nxt][r * 36 + c], gA + (long)(rowBase + r) * DH + k0 + c);
                cp16(&sBb[nxt][r * 36 + c], gB + (long)(colBase + r) * DH + k0 + c);
            }
            cp_commit();
            cp_wait<1>();
        } else {
            cp_wait<0>();
        }
        __syncthreads();

        const uint32_t* sA = sAb[cur];
        const uint32_t* sB = sBb[cur];

        #pragma unroll
        for (int kk = 0; kk < 4; kk++) {
            int row = warpM * 16;
            uint32_t a0 = sA[(row + g) * 36 + kk * 8 + t];
            uint32_t a1 = sA[(row + 8 + g) * 36 + kk * 8 + t];
            uint32_t a2 = sA[(row + g) * 36 + kk * 8 + t + 4];
            uint32_t a3 = sA[(row + 8 + g) * 36 + kk * 8 + t + 4];
            #pragma unroll
            for (int nt = 0; nt < 4; nt++) {
                int col = warpN * 32 + nt * 8;
                uint32_t b0 = sB[(col + g) * 36 + kk * 8 + t];
                uint32_t b1 = sB[(col + g) * 36 + kk * 8 + t + 4];
                mma8(acc[nt], a0, a1, a2, a3, b0, b1);
            }
        }
        __syncthreads();
    }

    #pragma unroll
    for (int nt = 0; nt < 4; nt++) {
        int col = colBase + warpN * 32 + nt * 8 + 2 * t;
        float b0v = pb[col], b1v = pb[col + 1];
        int row0 = rowBase + warpM * 16 + g;
        int row1 = row0 + 8;
        float2 lo = {acc[nt][0] + b0v, acc[nt][1] + b1v};
        float2 hi = {acc[nt][2] + b0v, acc[nt][3] + b1v};
        *(float2*)&out[row0 * DIMX + col] = lo;
        *(float2*)&out[row1 * DIMX + col] = hi;
    }
}

// ---------------------------------------------------------------------------
extern "C" void kernel_launch(void* const* d_in, const int* in_sizes, int n_in,
                              void* d_out, int out_size)
{
    const float* x       = (const float*)d_in[0];
    const float* q_w     = (const float*)d_in[1];
    const float* q_b     = (const float*)d_in[2];
    const float* k_w     = (const float*)d_in[3];
    const float* k_b     = (const float*)d_in[4];
    const float* v_w     = (const float*)d_in[5];
    const float* v_b     = (const float*)d_in[6];
    const float* proj_w  = (const float*)d_in[7];
    const float* proj_b  = (const float*)d_in[8];
    const float* biases  = (const float*)d_in[9];
    float* out = (float*)d_out;

    conv_w<<<(DIMX * DH / 4) / 256, 256>>>(proj_w);

    qkv_mma<<<dim3(N_TOK / 128, 1536 / 64), 256>>>(x, q_w, q_b, k_w, k_b, v_w, v_b);

    const size_t smemAttn = AT_TOTAL * sizeof(uint32_t);
    cudaFuncSetAttribute(attn_mma, cudaFuncAttributeMaxDynamicSharedMemorySize,
                         (int)smemAttn);
    attn_mma<<<dim3(N_TOK / 64, NHEADS), 256, smemAttn>>>(biases);

    proj_mma<<<dim3(N_TOK / 64, DIMX / 64), 256>>>(proj_b, out);
}

// round 17
// speedup vs baseline: 1.3078x; 1.3078x over previous
#include <cuda_runtime.h>
#include <cstdint>

#define N_TOK 2304
#define DIMX 384
#define NHEADS 8
#define KD 32
#define DV 128
#define DH 1024
#define RES 48
#define SCALE_F 0.17677669529663687f

// Scratch (allocation-free rule: __device__ globals)
// g_Q/g_K/g_V/g_O/g_Wp hold tf32-rounded bit patterns.
__device__ float g_Q[NHEADS * N_TOK * KD];
__device__ float g_K[NHEADS * N_TOK * KD];
__device__ float g_V[NHEADS * N_TOK * DV];
__device__ float g_O[N_TOK * DH];              // tf32 bits (attn output)
__device__ float g_Wp[DIMX * DH];              // tf32 bits (proj_w converted)

// ---------------------------------------------------------------------------
// helpers
// ---------------------------------------------------------------------------
__device__ __forceinline__ uint32_t f2tf(float f) {
    uint32_t u;
    asm("cvt.rna.tf32.f32 %0, %1;" : "=r"(u) : "f"(f));
    return u;
}

__device__ __forceinline__ void mma8(float* d,
                                     uint32_t a0, uint32_t a1, uint32_t a2, uint32_t a3,
                                     uint32_t b0, uint32_t b1)
{
    asm volatile(
        "mma.sync.aligned.m16n8k8.row.col.f32.tf32.tf32.f32 "
        "{%0,%1,%2,%3}, {%4,%5,%6,%7}, {%8,%9}, {%0,%1,%2,%3};\n"
        : "+f"(d[0]), "+f"(d[1]), "+f"(d[2]), "+f"(d[3])
        : "r"(a0), "r"(a1), "r"(a2), "r"(a3), "r"(b0), "r"(b1));
}

__device__ __forceinline__ void cp16(uint32_t* smem_dst, const void* gsrc) {
    uint32_t sa = (uint32_t)__cvta_generic_to_shared(smem_dst);
    asm volatile("cp.async.cg.shared.global [%0], [%1], 16;\n" :: "r"(sa), "l"(gsrc));
}
__device__ __forceinline__ void cp_commit() {
    asm volatile("cp.async.commit_group;\n");
}
template <int N>
__device__ __forceinline__ void cp_wait() {
    asm volatile("cp.async.wait_group %0;\n" :: "n"(N));
}

// ---------------------------------------------------------------------------
// Kernel 0: convert proj_w to tf32 bits (one shot, ~2 us).
// ---------------------------------------------------------------------------
__global__ __launch_bounds__(256) void conv_w(const float* __restrict__ Wp)
{
    int i = blockIdx.x * 256 + threadIdx.x;      // 98304 float4s
    float4 w = ((const float4*)Wp)[i];
    uint4 u = {f2tf(w.x), f2tf(w.y), f2tf(w.z), f2tf(w.w)};
    ((uint4*)g_Wp)[i] = u;
}

// ---------------------------------------------------------------------------
// Kernel 1: fused QKV projection — exact R10 form (proven).
// ---------------------------------------------------------------------------
__global__ __launch_bounds__(256) void qkv_mma(
    const float* __restrict__ x,
    const float* __restrict__ q_w, const float* __restrict__ q_b,
    const float* __restrict__ k_w, const float* __restrict__ k_b,
    const float* __restrict__ v_w, const float* __restrict__ v_b)
{
    __shared__ __align__(16) uint32_t sA[128 * 36];
    __shared__ __align__(16) uint32_t sB[64 * 36];

    const int tid  = threadIdx.x;
    const int warp = tid >> 5, lane = tid & 31;
    const int g = lane >> 2, t = lane & 3;
    const int warpM = warp & 3;
    const int warpN = warp >> 2;
    const int rowBase = blockIdx.x * 128;
    const int colBase = blockIdx.y * 64;

    const float* W; const float* bias; int sel, wBase;
    if (colBase < 256)      { W = q_w; bias = q_b; sel = 0; wBase = colBase;       }
    else if (colBase < 512) { W = k_w; bias = k_b; sel = 1; wBase = colBase - 256; }
    else                    { W = v_w; bias = v_b; sel = 2; wBase = colBase - 512; }

    float acc[2][4][4];
    #pragma unroll
    for (int mt = 0; mt < 2; mt++)
        #pragma unroll
        for (int nt = 0; nt < 4; nt++)
            #pragma unroll
            for (int j = 0; j < 4; j++) acc[mt][nt][j] = 0.f;

    for (int k0 = 0; k0 < DIMX; k0 += 32) {
        #pragma unroll
        for (int it = 0; it < 4; it++) {
            int i = tid + it * 256;
            int r = i >> 3, c = (i & 7) << 2;
            float4 a = *(const float4*)(x + (rowBase + r) * DIMX + k0 + c);
            uint4 u = {f2tf(a.x), f2tf(a.y), f2tf(a.z), f2tf(a.w)};
            *(uint4*)&sA[r * 36 + c] = u;
        }
        #pragma unroll
        for (int it = 0; it < 2; it++) {
            int i = tid + it * 256;
            int r = i >> 3, c = (i & 7) << 2;
            float4 b = *(const float4*)(W + (wBase + r) * DIMX + k0 + c);
            uint4 u = {f2tf(b.x), f2tf(b.y), f2tf(b.z), f2tf(b.w)};
            *(uint4*)&sB[r * 36 + c] = u;
        }
        __syncthreads();

        #pragma unroll
        for (int kk = 0; kk < 4; kk++) {
            uint32_t af[2][4], bf[4][2];
            #pragma unroll
            for (int mt = 0; mt < 2; mt++) {
                int row = warpM * 32 + mt * 16;
                af[mt][0] = sA[(row + g) * 36 + kk * 8 + t];
                af[mt][1] = sA[(row + 8 + g) * 36 + kk * 8 + t];
                af[mt][2] = sA[(row + g) * 36 + kk * 8 + t + 4];
                af[mt][3] = sA[(row + 8 + g) * 36 + kk * 8 + t + 4];
            }
            #pragma unroll
            for (int nt = 0; nt < 4; nt++) {
                int col = warpN * 32 + nt * 8;
                bf[nt][0] = sB[(col + g) * 36 + kk * 8 + t];
                bf[nt][1] = sB[(col + g) * 36 + kk * 8 + t + 4];
            }
            #pragma unroll
            for (int mt = 0; mt < 2; mt++)
                #pragma unroll
                for (int nt = 0; nt < 4; nt++)
                    mma8(acc[mt][nt], af[mt][0], af[mt][1], af[mt][2], af[mt][3],
                         bf[nt][0], bf[nt][1]);
        }
        __syncthreads();
    }

    #pragma unroll
    for (int nt = 0; nt < 4; nt++) {
        int jl = wBase + warpN * 32 + nt * 8 + 2 * t;
        float b0v = bias[jl], b1v = bias[jl + 1];
        #pragma unroll
        for (int mt = 0; mt < 2; mt++) {
            int row0 = rowBase + warpM * 32 + mt * 16 + g;
            int row1 = row0 + 8;
            float2 lo = {__uint_as_float(f2tf(acc[mt][nt][0] + b0v)),
                         __uint_as_float(f2tf(acc[mt][nt][1] + b1v))};
            float2 hi = {__uint_as_float(f2tf(acc[mt][nt][2] + b0v)),
                         __uint_as_float(f2tf(acc[mt][nt][3] + b1v))};
            if (sel == 0) {
                int h = jl >> 5, kd = jl & 31;
                *(float2*)&g_Q[(h * N_TOK + row0) * KD + kd] = lo;
                *(float2*)&g_Q[(h * N_TOK + row1) * KD + kd] = hi;
            } else if (sel == 1) {
                int h = jl >> 5, kd = jl & 31;
                *(float2*)&g_K[(h * N_TOK + row0) * KD + kd] = lo;
                *(float2*)&g_K[(h * N_TOK + row1) * KD + kd] = hi;
            } else {
                int h = jl >> 7, dv = jl & 127;
                *(float2*)&g_V[(h * N_TOK + row0) * DV + dv] = lo;
                *(float2*)&g_V[(h * N_TOK + row1) * DV + dv] = hi;
            }
        }
    }
}

// ---------------------------------------------------------------------------
// Kernel 2: flash attention, BK=128 (18 iterations instead of 36).
// BQ=128, 256 threads, grid (18, 8) = 144 CTAs, 1 CTA/SM (198 KB smem).
// Per-iter fixed overhead (barriers, shuffles, rescale, sAlpha/sL) halved.
// K double-buffered; V single-buffered with deferred wait (R15 mechanics).
// Softmax: warp owns 16 rows. PV: 4 rowgroups x 2 colgroups (R6 retile).
// ---------------------------------------------------------------------------
#define KBUF (128 * 36)
#define AT_SQ     0                          // 128*36 = 4608
#define AT_SK     (AT_SQ + 128 * 36)         // 2 x 4608
#define AT_SV     (AT_SK + 2 * KBUF)         // 128*136 = 17408
#define AT_SS     (AT_SV + 128 * 136)        // 128*132 = 16896
#define AT_SBIAS  (AT_SS + 128 * 132)        // 2304
#define AT_SALPHA (AT_SBIAS + N_TOK)         // 128
#define AT_SL     (AT_SALPHA + 128)          // 128
#define AT_TOTAL  (AT_SL + 128)              // 50688 u32 = 202752 bytes

__global__ __launch_bounds__(256, 1) void attn_mma(
    const float* __restrict__ biases)
{
    extern __shared__ __align__(16) uint32_t smu[];
    uint32_t* sQ  = smu + AT_SQ;
    uint32_t* sKb = smu + AT_SK;
    uint32_t* sV  = smu + AT_SV;
    uint32_t* sS  = smu + AT_SS;
    float*    sBias  = (float*)(smu + AT_SBIAS);
    float*    sAlpha = (float*)(smu + AT_SALPHA);
    float*    sL     = (float*)(smu + AT_SL);

    const int tid  = threadIdx.x;
    const int warp = tid >> 5, lane = tid & 31;
    const int g = lane >> 2, t = lane & 3;
    const int h  = blockIdx.y;
    const int q0 = blockIdx.x * 128;

    const uint32_t* gK = (const uint32_t*)(g_K + h * N_TOK * KD);
    const uint32_t* gV = (const uint32_t*)(g_V + h * N_TOK * DV);

    // --- prologue: Q tile + bias -> smem, prefetch K(0) ---
    {
        const uint4* src = (const uint4*)(g_Q + (h * N_TOK + q0) * KD);
        #pragma unroll
        for (int it = 0; it < 4; it++) {
            int i = tid + it * 256;          // 1024 uint4s
            int r = i >> 3, c = (i & 7) << 2;
            *(uint4*)&sQ[r * 36 + c] = src[i];
        }
        #pragma unroll
        for (int it = 0; it < 9; it++)
            sBias[tid + it * 256] = biases[h * N_TOK + tid + it * 256];
        // K(0): 128x32 u32 = 1024 cp16s
        #pragma unroll
        for (int it = 0; it < 4; it++) {
            int i = tid + it * 256;
            int r = i >> 3, c = (i & 7) << 2;
            cp16(&sKb[r * 36 + c], gK + i * 4);
        }
        cp_commit();
    }
    __syncthreads();   // sQ visible

    // --- Q fragments, register resident ---
    uint32_t qf[4][4];
    {
        int row = 16 * warp + g;
        #pragma unroll
        for (int kk = 0; kk < 4; kk++) {
            qf[kk][0] = sQ[row * 36 + kk * 8 + t];
            qf[kk][1] = sQ[(row + 8) * 36 + kk * 8 + t];
            qf[kk][2] = sQ[row * 36 + kk * 8 + t + 4];
            qf[kk][3] = sQ[(row + 8) * 36 + kk * 8 + t + 4];
        }
    }

    float m0 = -1e30f, m1 = -1e30f, l0 = 0.f, l1 = 0.f;

    // PV tiling: 4 rowgroups x 2 colgroups, O = 32 rows x 64 cols per warp.
    const int prow = (warp >> 1) * 32;
    const int pcol = (warp & 1) * 64;
    float o[2][8][4];
    #pragma unroll
    for (int mt = 0; mt < 2; mt++)
        #pragma unroll
        for (int vt = 0; vt < 8; vt++)
            #pragma unroll
            for (int j = 0; j < 4; j++) o[mt][vt][j] = 0.f;

    const int rowW = 16 * warp + g;
    const int gRow0 = q0 + rowW;
    const int gRow1 = gRow0 + 8;
    const int qy0 = gRow0 / RES, qx0 = gRow0 - qy0 * RES;
    const int qy1 = gRow1 / RES, qx1 = gRow1 - qy1 * RES;

    const int NITER = N_TOK / 128;   // 18

    for (int ki = 0; ki < NITER; ki++) {
        const int cur = ki & 1, nxt = cur ^ 1;
        const bool hasNext = (ki + 1 < NITER);

        // issue V(ki) into single V buffer (128x128 u32 = 4096 cp16s)
        {
            const uint32_t* gVn = gV + ki * 128 * DV;
            #pragma unroll
            for (int it = 0; it < 16; it++) {
                int i = tid + it * 256;
                int r = i >> 5, c = (i & 31) << 2;
                cp16(&sV[r * 136 + c], gVn + i * 4);
            }
            cp_commit();
        }
        // issue K(ki+1)
        if (hasNext) {
            const uint32_t* gKn = gK + (ki + 1) * 128 * KD;
            #pragma unroll
            for (int it = 0; it < 4; it++) {
                int i = tid + it * 256;
                int r = i >> 3, c = (i & 7) << 2;
                cp16(&sKb[nxt * KBUF + r * 36 + c], gKn + i * 4);
            }
            cp_commit();
        }
        // wait for K(ki); leave V(ki) [+ K(ki+1)] in flight
        if (hasNext) cp_wait<2>(); else cp_wait<1>();
        __syncthreads();

        const uint32_t* sK = sKb + cur * KBUF;
        const int k0 = ki * 128;

        // --- S = Q @ K^T (warp's 16 rows x 128 cols) + scale + computed bias ---
        float sreg[16][4];
        #pragma unroll
        for (int nt = 0; nt < 16; nt++) {
            float s4[4] = {0.f, 0.f, 0.f, 0.f};
            #pragma unroll
            for (int kk = 0; kk < 4; kk++) {
                uint32_t b0 = sK[(nt * 8 + g) * 36 + kk * 8 + t];
                uint32_t b1 = sK[(nt * 8 + g) * 36 + kk * 8 + t + 4];
                mma8(s4, qf[kk][0], qf[kk][1], qf[kk][2], qf[kk][3], b0, b1);
            }
            int c0 = k0 + nt * 8 + 2 * t;
            int c1 = c0 + 1;
            int ky0 = c0 / RES, kx0 = c0 - ky0 * RES;
            int ky1 = c1 / RES, kx1 = c1 - ky1 * RES;
            sreg[nt][0] = s4[0] * SCALE_F + sBias[abs(qy0 - ky0) * RES + abs(qx0 - kx0)];
            sreg[nt][1] = s4[1] * SCALE_F + sBias[abs(qy0 - ky1) * RES + abs(qx0 - kx1)];
            sreg[nt][2] = s4[2] * SCALE_F + sBias[abs(qy1 - ky0) * RES + abs(qx1 - kx0)];
            sreg[nt][3] = s4[3] * SCALE_F + sBias[abs(qy1 - ky1) * RES + abs(qx1 - kx1)];
        }

        // --- online softmax (one update per 128 cols) ---
        float mx0 = m0, mx1 = m1;
        #pragma unroll
        for (int nt = 0; nt < 16; nt++) {
            mx0 = fmaxf(mx0, fmaxf(sreg[nt][0], sreg[nt][1]));
            mx1 = fmaxf(mx1, fmaxf(sreg[nt][2], sreg[nt][3]));
        }
        mx0 = fmaxf(mx0, __shfl_xor_sync(0xffffffffu, mx0, 1));
        mx0 = fmaxf(mx0, __shfl_xor_sync(0xffffffffu, mx0, 2));
        mx1 = fmaxf(mx1, __shfl_xor_sync(0xffffffffu, mx1, 1));
        mx1 = fmaxf(mx1, __shfl_xor_sync(0xffffffffu, mx1, 2));
        float a0 = __expf(m0 - mx0), a1 = __expf(m1 - mx1);
        float sum0 = 0.f, sum1 = 0.f;
        #pragma unroll
        for (int nt = 0; nt < 16; nt++) {
            float p0 = __expf(sreg[nt][0] - mx0);
            float p1 = __expf(sreg[nt][1] - mx0);
            float p2 = __expf(sreg[nt][2] - mx1);
            float p3 = __expf(sreg[nt][3] - mx1);
            sum0 += p0 + p1; sum1 += p2 + p3;
            uint2 u0 = {f2tf(p0), f2tf(p1)};
            uint2 u1 = {f2tf(p2), f2tf(p3)};
            *(uint2*)&sS[rowW * 132 + nt * 8 + 2 * t] = u0;
            *(uint2*)&sS[(rowW + 8) * 132 + nt * 8 + 2 * t] = u1;
        }
        sum0 += __shfl_xor_sync(0xffffffffu, sum0, 1);
        sum0 += __shfl_xor_sync(0xffffffffu, sum0, 2);
        sum1 += __shfl_xor_sync(0xffffffffu, sum1, 1);
        sum1 += __shfl_xor_sync(0xffffffffu, sum1, 2);
        l0 = l0 * a0 + sum0; m0 = mx0;
        l1 = l1 * a1 + sum1; m1 = mx1;
        if (t == 0) {
            sAlpha[rowW] = a0;
            sAlpha[rowW + 8] = a1;
        }

        // wait for V(ki) — latency covered by S + softmax
        if (hasNext) cp_wait<1>(); else cp_wait<0>();
        __syncthreads();   // sS + sAlpha + sV visible

        // --- rescale O (PV tiling rows) ---
        #pragma unroll
        for (int mt = 0; mt < 2; mt++) {
            float al0 = sAlpha[prow + mt * 16 + g];
            float al1 = sAlpha[prow + mt * 16 + 8 + g];
            #pragma unroll
            for (int vt = 0; vt < 8; vt++) {
                o[mt][vt][0] *= al0; o[mt][vt][1] *= al0;
                o[mt][vt][2] *= al1; o[mt][vt][3] *= al1;
            }
        }

        // --- O += P @ V (16 k-steps) ---
        #pragma unroll
        for (int kk = 0; kk < 16; kk++) {
            uint32_t pa[2][4];
            #pragma unroll
            for (int mt = 0; mt < 2; mt++) {
                int r = prow + mt * 16 + g;
                pa[mt][0] = sS[r * 132 + kk * 8 + t];
                pa[mt][1] = sS[(r + 8) * 132 + kk * 8 + t];
                pa[mt][2] = sS[r * 132 + kk * 8 + t + 4];
                pa[mt][3] = sS[(r + 8) * 132 + kk * 8 + t + 4];
            }
            #pragma unroll
            for (int vt = 0; vt < 8; vt++) {
                uint32_t b0 = sV[(kk * 8 + t) * 136 + pcol + vt * 8 + g];
                uint32_t b1 = sV[(kk * 8 + t + 4) * 136 + pcol + vt * 8 + g];
                mma8(o[0][vt], pa[0][0], pa[0][1], pa[0][2], pa[0][3], b0, b1);
                mma8(o[1][vt], pa[1][0], pa[1][1], pa[1][2], pa[1][3], b0, b1);
            }
        }
        __syncthreads();   // sV + sS reads done before next-iter refill
    }

    // --- finalize ---
    if (t == 0) {
        sL[rowW] = l0;
        sL[rowW + 8] = l1;
    }
    __syncthreads();
    #pragma unroll
    for (int mt = 0; mt < 2; mt++) {
        int r0 = prow + mt * 16 + g;
        int r1 = r0 + 8;
        float inv0 = 1.f / sL[r0];
        float inv1 = 1.f / sL[r1];
        #pragma unroll
        for (int vt = 0; vt < 8; vt++) {
            int col = pcol + vt * 8 + 2 * t;
            float2 lo = {__uint_as_float(f2tf(o[mt][vt][0] * inv0)),
                         __uint_as_float(f2tf(o[mt][vt][1] * inv0))};
            float2 hi = {__uint_as_float(f2tf(o[mt][vt][2] * inv1)),
                         __uint_as_float(f2tf(o[mt][vt][3] * inv1))};
            *(float2*)&g_O[(long)(q0 + r0) * DH + h * DV + col] = lo;
            *(float2*)&g_O[(long)(q0 + r1) * DH + h * DV + col] = hi;
        }
    }
}

// ---------------------------------------------------------------------------
// Kernel 3: output projection — unchanged from R10 (30.3 us).
// ---------------------------------------------------------------------------
#define PJBUF (64 * 36)

__global__ __launch_bounds__(256, 2) void proj_mma(
    const float* __restrict__ pb, float* __restrict__ out)
{
    __shared__ __align__(16) uint32_t sAb[2][PJBUF];
    __shared__ __align__(16) uint32_t sBb[2][PJBUF];

    const int tid  = threadIdx.x;
    const int warp = tid >> 5, lane = tid & 31;
    const int g = lane >> 2, t = lane & 3;
    const int warpM = warp & 3;
    const int warpN = warp >> 2;
    const int rowBase = blockIdx.x * 64;
    const int colBase = blockIdx.y * 64;

    const uint32_t* gA = (const uint32_t*)g_O;
    const uint32_t* gB = (const uint32_t*)g_Wp;

    float acc[4][4];
    #pragma unroll
    for (int nt = 0; nt < 4; nt++)
        #pragma unroll
        for (int j = 0; j < 4; j++) acc[nt][j] = 0.f;

    {
        #pragma unroll
        for (int it = 0; it < 2; it++) {
            int i = tid + it * 256;
            int r = i >> 3, c = (i & 7) << 2;
            cp16(&sAb[0][r * 36 + c], gA + (long)(rowBase + r) * DH + c);
            cp16(&sBb[0][r * 36 + c], gB + (long)(colBase + r) * DH + c);
        }
        cp_commit();
    }

    const int NIT = DH / 32;   // 32
    for (int ki = 0; ki < NIT; ki++) {
        const int cur = ki & 1, nxt = cur ^ 1;
        if (ki + 1 < NIT) {
            int k0 = (ki + 1) * 32;
            #pragma unroll
            for (int it = 0; it < 2; it++) {
                int i = tid + it * 256;
                int r = i >> 3, c = (i & 7) << 2;
                cp16(&sAb[nxt][r * 36 + c], gA + (long)(rowBase + r) * DH + k0 + c);
                cp16(&sBb[nxt][r * 36 + c], gB + (long)(colBase + r) * DH + k0 + c);
            }
            cp_commit();
            cp_wait<1>();
        } else {
            cp_wait<0>();
        }
        __syncthreads();

        const uint32_t* sA = sAb[cur];
        const uint32_t* sB = sBb[cur];

        #pragma unroll
        for (int kk = 0; kk < 4; kk++) {
            int row = warpM * 16;
            uint32_t a0 = sA[(row + g) * 36 + kk * 8 + t];
            uint32_t a1 = sA[(row + 8 + g) * 36 + kk * 8 + t];
            uint32_t a2 = sA[(row + g) * 36 + kk * 8 + t + 4];
            uint32_t a3 = sA[(row + 8 + g) * 36 + kk * 8 + t + 4];
            #pragma unroll
            for (int nt = 0; nt < 4; nt++) {
                int col = warpN * 32 + nt * 8;
                uint32_t b0 = sB[(col + g) * 36 + kk * 8 + t];
                uint32_t b1 = sB[(col + g) * 36 + kk * 8 + t + 4];
                mma8(acc[nt], a0, a1, a2, a3, b0, b1);
            }
        }
        __syncthreads();
    }

    #pragma unroll
    for (int nt = 0; nt < 4; nt++) {
        int col = colBase + warpN * 32 + nt * 8 + 2 * t;
        float b0v = pb[col], b1v = pb[col + 1];
        int row0 = rowBase + warpM * 16 + g;
        int row1 = row0 + 8;
        float2 lo = {acc[nt][0] + b0v, acc[nt][1] + b1v};
        float2 hi = {acc[nt][2] + b0v, acc[nt][3] + b1v};
        *(float2*)&out[row0 * DIMX + col] = lo;
        *(float2*)&out[row1 * DIMX + col] = hi;
    }
}

// ---------------------------------------------------------------------------
extern "C" void kernel_launch(void* const* d_in, const int* in_sizes, int n_in,
                              void* d_out, int out_size)
{
    const float* x       = (const float*)d_in[0];
    const float* q_w     = (const float*)d_in[1];
    const float* q_b     = (const float*)d_in[2];
    const float* k_w     = (const float*)d_in[3];
    const float* k_b     = (const float*)d_in[4];
    const float* v_w     = (const float*)d_in[5];
    const float* v_b     = (const float*)d_in[6];
    const float* proj_w  = (const float*)d_in[7];
    const float* proj_b  = (const float*)d_in[8];
    const float* biases  = (const float*)d_in[9];
    float* out = (float*)d_out;

    conv_w<<<(DIMX * DH / 4) / 256, 256>>>(proj_w);

    qkv_mma<<<dim3(N_TOK / 128, 1536 / 64), 256>>>(x, q_w, q_b, k_w, k_b, v_w, v_b);

    const size_t smemAttn = AT_TOTAL * sizeof(uint32_t);
    cudaFuncSetAttribute(attn_mma, cudaFuncAttributeMaxDynamicSharedMemorySize,
                         (int)smemAttn);
    attn_mma<<<dim3(N_TOK / 128, NHEADS), 256, smemAttn>>>(biases);

    proj_mma<<<dim3(N_TOK / 64, DIMX / 64), 256>>>(proj_b, out);
}